// round 6
// baseline (speedup 1.0000x reference)
#include <cuda_runtime.h>

#define DEV_INLINE __device__ __forceinline__
typedef unsigned long long ull;

constexpr int C  = 8;
constexpr int K  = 64;
constexpr int NN = 2048;

// ---- per-(c,k) repacked blob layout (floats) ----
constexpr int BLOB = 5632;               // 22528 B
constexpr int W1S = 0;                   // [64][20] stride-padded, cols 0..15 valid
constexpr int W1T = 1280;
constexpr int W2S = 2560;                // transposed [i][r], stride 20
constexpr int W2T = 3840;
constexpr int B1S = 5120, B1T = 5184;
constexpr int B2S = 5248, B2T = 5264;    // passive order
constexpr int ANE = 5280;                // [act 16 | pas 16] exp(-s)
constexpr int ANF = 5312;                // [act 16 | pas 16] -t*exp(-s)
constexpr int ASUM = 5344;

__device__ float g_blob[C * K * BLOB];
__device__ float g_Bm[C * NN];
__device__ float g_Sn[C * C];

// ---------- packed f32x2 helpers ----------
DEV_INLINE ull pack2(float lo, float hi) {
    ull r; asm("mov.b64 %0, {%1,%2};" : "=l"(r) : "f"(lo), "f"(hi)); return r;
}
DEV_INLINE void unpack2(ull v, float& lo, float& hi) {
    asm("mov.b64 {%0,%1}, %2;" : "=f"(lo), "=f"(hi) : "l"(v));
}
DEV_INLINE ull ffma2(ull a, ull b, ull c) {
    ull d; asm("fma.rn.f32x2 %0, %1, %2, %3;" : "=l"(d) : "l"(a), "l"(b), "l"(c)); return d;
}
DEV_INLINE ull add2(ull a, ull b) {
    ull d; asm("add.rn.f32x2 %0, %1, %2;" : "=l"(d) : "l"(a), "l"(b)); return d;
}
DEV_INLINE ull mul2(ull a, ull b) {
    ull d; asm("mul.rn.f32x2 %0, %1, %2;" : "=l"(d) : "l"(a), "l"(b)); return d;
}
DEV_INLINE ull neg2(ull a) { return a ^ 0x8000000080000000ULL; }

// ---------- repack: gather/compact/transpose weights once ----------
__global__ void __launch_bounds__(128)
repack_kernel(const float* __restrict__ sW1, const float* __restrict__ sb1,
              const float* __restrict__ sW2, const float* __restrict__ sb2,
              const float* __restrict__ tW1, const float* __restrict__ tb1,
              const float* __restrict__ tW2, const float* __restrict__ tb2,
              const float* __restrict__ anS, const float* __restrict__ anT)
{
    const int ck = blockIdx.x;          // c*64+k
    const int k = ck & 63;
    const int A = k & 1, PO = 1 - A;    // active / passive parity
    float* B = g_blob + (size_t)ck * BLOB;
    const int tid = threadIdx.x;
    const size_t wo = (size_t)ck * 2048;

    for (int idx = tid; idx < 1024; idx += 128) {
        int i = idx >> 4, j = idx & 15;
        B[W1S + i * 20 + j] = sW1[wo + i * 32 + 2 * j + A];
        B[W1T + i * 20 + j] = tW1[wo + i * 32 + 2 * j + A];
        B[W2S + i * 20 + j] = sW2[wo + (2 * j + PO) * 64 + i];
        B[W2T + i * 20 + j] = tW2[wo + (2 * j + PO) * 64 + i];
    }
    if (tid < 64) {
        B[B1S + tid] = sb1[ck * 64 + tid];
        B[B1T + tid] = tb1[ck * 64 + tid];
    } else if (tid < 80) {
        int r = tid - 64;
        B[B2S + r] = sb2[ck * 32 + 2 * r + PO];
        B[B2T + r] = tb2[ck * 32 + 2 * r + PO];
    } else if (tid < 112) {
        int q = tid - 80;               // 0..31: [act 16 | pas 16]
        int dim = (q < 16) ? (2 * q + A) : (2 * (q - 16) + PO);
        float a = anS[ck * 32 + dim];
        float t = anT[ck * 32 + dim];
        float e = __expf(-a);
        B[ANE + q] = e;
        B[ANF + q] = -t * e;
    } else if (tid == 112) {
        float s = 0.f;
        for (int d = 0; d < 32; d++) s += anS[ck * 32 + d];
        B[ASUM] = s;
    }
}

// ---------- one inverse layer: quarter-split hidden, 2 nodes/thread ----------
// Weights read straight from L1/L2 via uniform LDG — no shared memory at all.
DEV_INLINE void layer_compute(const float* __restrict__ gb, int q,
                              ull (&a0)[8], ull (&p0)[8],
                              ull (&a1)[8], ull (&p1)[8],
                              float& ld0, float& ld1)
{
    // ActNorm inverse (E/F stored in act|pas order)
    const ulonglong2* E2 = (const ulonglong2*)(gb + ANE);
    const ulonglong2* F2 = (const ulonglong2*)(gb + ANF);
    #pragma unroll
    for (int h = 0; h < 4; h++) {
        ulonglong2 ea = __ldg(E2 + h),     fa = __ldg(F2 + h);
        ulonglong2 ep = __ldg(E2 + 4 + h), fp = __ldg(F2 + 4 + h);
        a0[2*h]   = ffma2(a0[2*h],   ea.x, fa.x);
        a0[2*h+1] = ffma2(a0[2*h+1], ea.y, fa.y);
        a1[2*h]   = ffma2(a1[2*h],   ea.x, fa.x);
        a1[2*h+1] = ffma2(a1[2*h+1], ea.y, fa.y);
        p0[2*h]   = ffma2(p0[2*h],   ep.x, fp.x);
        p0[2*h+1] = ffma2(p0[2*h+1], ep.y, fp.y);
        p1[2*h]   = ffma2(p1[2*h],   ep.x, fp.x);
        p1[2*h+1] = ffma2(p1[2*h+1], ep.y, fp.y);
    }
    float asum = __ldg(gb + ASUM);
    ld0 -= asum; ld1 -= asum;

    // accumulators (16 outputs as 8 packed pairs) per node
    ull s0[8], t0[8], s1[8], t1[8];
    const ulonglong2* b2s = (const ulonglong2*)(gb + B2S);
    const ulonglong2* b2t = (const ulonglong2*)(gb + B2T);
    #pragma unroll
    for (int h = 0; h < 4; h++) {
        ulonglong2 bs = __ldg(b2s + h), bt = __ldg(b2t + h);
        ull vs0 = (q == 0) ? bs.x : 0ULL;
        ull vs1 = (q == 0) ? bs.y : 0ULL;
        ull vt0 = (q == 0) ? bt.x : 0ULL;
        ull vt1 = (q == 0) ? bt.y : 0ULL;
        s0[2*h] = vs0; s0[2*h+1] = vs1; s1[2*h] = vs0; s1[2*h+1] = vs1;
        t0[2*h] = vt0; t0[2*h+1] = vt1; t1[2*h] = vt0; t1[2*h+1] = vt1;
    }

    #pragma unroll 4
    for (int il = 0; il < 16; il++) {
        const int gi = il * 4 + q;                  // this thread's hidden unit
        const ulonglong2* r1s = (const ulonglong2*)(gb + W1S + gi * 20);
        const ulonglong2* r1t = (const ulonglong2*)(gb + W1T + gi * 20);
        ull as0 = pack2(__ldg(gb + B1S + gi), 0.f);
        ull at0 = pack2(__ldg(gb + B1T + gi), 0.f);
        ull as1 = as0, at1 = at0;
        #pragma unroll
        for (int ch = 0; ch < 4; ch++) {
            ulonglong2 ws = __ldg(r1s + ch), wt = __ldg(r1t + ch);
            as0 = ffma2(ws.x, a0[2*ch],   as0);
            as0 = ffma2(ws.y, a0[2*ch+1], as0);
            as1 = ffma2(ws.x, a1[2*ch],   as1);
            as1 = ffma2(ws.y, a1[2*ch+1], as1);
            at0 = ffma2(wt.x, a0[2*ch],   at0);
            at0 = ffma2(wt.y, a0[2*ch+1], at0);
            at1 = ffma2(wt.x, a1[2*ch],   at1);
            at1 = ffma2(wt.y, a1[2*ch+1], at1);
        }
        float x0, x1;
        unpack2(as0, x0, x1); float hs0 = fmaxf(x0 + x1, 0.f);
        unpack2(as1, x0, x1); float hs1 = fmaxf(x0 + x1, 0.f);
        unpack2(at0, x0, x1); float ht0 = fmaxf(x0 + x1, 0.f);
        unpack2(at1, x0, x1); float ht1 = fmaxf(x0 + x1, 0.f);
        ull hs0p = pack2(hs0, hs0), hs1p = pack2(hs1, hs1);
        ull ht0p = pack2(ht0, ht0), ht1p = pack2(ht1, ht1);

        const ulonglong2* r2s = (const ulonglong2*)(gb + W2S + gi * 20);
        const ulonglong2* r2t = (const ulonglong2*)(gb + W2T + gi * 20);
        #pragma unroll
        for (int ch = 0; ch < 4; ch++) {
            ulonglong2 ws = __ldg(r2s + ch), wt = __ldg(r2t + ch);
            s0[2*ch]   = ffma2(ws.x, hs0p, s0[2*ch]);
            s0[2*ch+1] = ffma2(ws.y, hs0p, s0[2*ch+1]);
            s1[2*ch]   = ffma2(ws.x, hs1p, s1[2*ch]);
            s1[2*ch+1] = ffma2(ws.y, hs1p, s1[2*ch+1]);
            t0[2*ch]   = ffma2(wt.x, ht0p, t0[2*ch]);
            t0[2*ch+1] = ffma2(wt.y, ht0p, t0[2*ch+1]);
            t1[2*ch]   = ffma2(wt.x, ht1p, t1[2*ch]);
            t1[2*ch+1] = ffma2(wt.y, ht1p, t1[2*ch+1]);
        }
    }

    // butterfly over the 4 quarter-threads
    #pragma unroll
    for (int j = 0; j < 8; j++) {
        s0[j] = add2(s0[j], __shfl_xor_sync(0xffffffffu, s0[j], 1));
        s0[j] = add2(s0[j], __shfl_xor_sync(0xffffffffu, s0[j], 2));
        t0[j] = add2(t0[j], __shfl_xor_sync(0xffffffffu, t0[j], 1));
        t0[j] = add2(t0[j], __shfl_xor_sync(0xffffffffu, t0[j], 2));
        s1[j] = add2(s1[j], __shfl_xor_sync(0xffffffffu, s1[j], 1));
        s1[j] = add2(s1[j], __shfl_xor_sync(0xffffffffu, s1[j], 2));
        t1[j] = add2(t1[j], __shfl_xor_sync(0xffffffffu, t1[j], 1));
        t1[j] = add2(t1[j], __shfl_xor_sync(0xffffffffu, t1[j], 2));
    }

    // passive update + logdet (redundant across quarters, consistent)
    #pragma unroll
    for (int j = 0; j < 8; j++) {
        float sa, sbv;
        unpack2(s0[j], sa, sbv);
        ld0 -= (sa + sbv);
        ull e2 = pack2(__expf(-sa), __expf(-sbv));
        p0[j] = ffma2(p0[j], e2, neg2(mul2(t0[j], e2)));
        unpack2(s1[j], sa, sbv);
        ld1 -= (sa + sbv);
        e2 = pack2(__expf(-sa), __expf(-sbv));
        p1[j] = ffma2(p1[j], e2, neg2(mul2(t1[j], e2)));
    }
}

__global__ void __launch_bounds__(64)
flow_kernel(const float* __restrict__ nodes,
            const float* __restrict__ loc, const float* __restrict__ lsc)
{
    const int tid  = threadIdx.x;
    const int q    = tid & 3;            // quarter of hidden units
    const int slot = tid >> 2;           // 0..15
    const int c    = blockIdx.y;
    const int n0   = blockIdx.x * 32 + slot;
    const int n1   = n0 + 16;

    // z packed by parity: ze[j]=(dims 4j,4j+2), zo[j]=(4j+1,4j+3)
    ull ze0[8], zo0[8], ze1[8], zo1[8];
    {
        const float4* np = (const float4*)(nodes + (size_t)n0 * 32);
        #pragma unroll
        for (int j = 0; j < 8; j++) {
            float4 v = np[j];
            ze0[j] = pack2(v.x, v.z); zo0[j] = pack2(v.y, v.w);
        }
        np = (const float4*)(nodes + (size_t)n1 * 32);
        #pragma unroll
        for (int j = 0; j < 8; j++) {
            float4 v = np[j];
            ze1[j] = pack2(v.x, v.z); zo1[j] = pack2(v.y, v.w);
        }
    }
    float ld0 = 0.f, ld1 = 0.f;

    const float* gb = g_blob + (size_t)(c * 64) * BLOB;

    #pragma unroll 1
    for (int k = 63; k > 0; k -= 2) {
        // layer k (odd): active = odd dims
        layer_compute(gb + (size_t)k * BLOB, q, zo0, ze0, zo1, ze1, ld0, ld1);
        // layer k-1 (even): active = even dims
        layer_compute(gb + (size_t)(k - 1) * BLOB, q, ze0, zo0, ze1, zo1, ld0, ld1);
    }

    // DiagGaussian log_prob
    float acc0 = 0.f, acc1 = 0.f;
    const float* lp = loc + c * 32;
    const float* sp = lsc + c * 32;
    #pragma unroll
    for (int j = 0; j < 8; j++) {
        float e0, e1, o0, o1;
        float z40[4], z41[4];
        unpack2(ze0[j], e0, e1); unpack2(zo0[j], o0, o1);
        z40[0] = e0; z40[1] = o0; z40[2] = e1; z40[3] = o1;
        unpack2(ze1[j], e0, e1); unpack2(zo1[j], o0, o1);
        z41[0] = e0; z41[1] = o0; z41[2] = e1; z41[3] = o1;
        #pragma unroll
        for (int b = 0; b < 4; b++) {
            int d = 4 * j + b;
            float ls = __ldg(sp + d);
            float es = __expf(-ls);
            float lc = __ldg(lp + d);
            float u0 = (z40[b] - lc) * es;
            float u1 = (z41[b] - lc) * es;
            acc0 += ls + 0.5f * u0 * u0;
            acc1 += ls + 0.5f * u1 * u1;
        }
    }
    if (q == 0) {
        g_Bm[c * NN + n0] = __expf(ld0 - 29.406037829f - acc0);
        g_Bm[c * NN + n1] = __expf(ld1 - 29.406037829f - acc1);
    }
}

// Fold L1 row-normalizers and softmax-normalized S into one 8x8 matrix.
__global__ void norm_kernel(const float* __restrict__ S_unc)
{
    __shared__ float sh_r[8];
    __shared__ float sh_e[64];
    const int tid = threadIdx.x;
    const int w = tid >> 5, lane = tid & 31;

    float s = 0.f;
    for (int i = lane; i < NN; i += 32) s += g_Bm[w * NN + i];
    #pragma unroll
    for (int o = 16; o; o >>= 1) s += __shfl_xor_sync(0xffffffffu, s, o);
    if (lane == 0) sh_r[w] = fmaxf(s, 1e-12f);
    if (tid < 64) sh_e[tid] = expf(S_unc[tid]);
    __syncthreads();
    if (tid < 64) {
        float tot = 0.f;
        #pragma unroll
        for (int i = 0; i < 64; i++) tot += sh_e[i];
        int c1 = tid >> 3, c2 = tid & 7;
        g_Sn[tid] = sh_e[tid] / (tot * sh_r[c1] * sh_r[c2]);
    }
}

__global__ void __launch_bounds__(256)
out_kernel(float* __restrict__ out)
{
    __shared__ float B1[8][64];
    __shared__ float B2[8][64];
    __shared__ float T2[8][64];
    const int tid = threadIdx.x;
    const int n10 = blockIdx.y * 64;
    const int n20 = blockIdx.x * 64;

    for (int t = tid; t < 512; t += 256) {
        int cc = t >> 6, j = t & 63;
        B1[cc][j] = g_Bm[cc * NN + n10 + j];
        B2[cc][j] = g_Bm[cc * NN + n20 + j];
    }
    __syncthreads();
    if (tid < 64) {
        #pragma unroll
        for (int c1 = 0; c1 < 8; c1++) {
            float a = 0.f;
            #pragma unroll
            for (int c2 = 0; c2 < 8; c2++)
                a = fmaf(g_Sn[c1 * 8 + c2], B2[c2][tid], a);
            T2[c1][tid] = a;
        }
    }
    __syncthreads();

    const int ty = tid >> 4, tx = tid & 15;
    float bv[4][8], tv[8][4];
    #pragma unroll
    for (int cc = 0; cc < 8; cc++) {
        #pragma unroll
        for (int p = 0; p < 4; p++) {
            bv[p][cc] = B1[cc][ty * 4 + p];
            tv[cc][p] = T2[cc][tx * 4 + p];
        }
    }
    #pragma unroll
    for (int p = 0; p < 4; p++) {
        float4 o = {0.f, 0.f, 0.f, 0.f};
        #pragma unroll
        for (int cc = 0; cc < 8; cc++) {
            o.x = fmaf(bv[p][cc], tv[cc][0], o.x);
            o.y = fmaf(bv[p][cc], tv[cc][1], o.y);
            o.z = fmaf(bv[p][cc], tv[cc][2], o.z);
            o.w = fmaf(bv[p][cc], tv[cc][3], o.w);
        }
        *((float4*)(out + (size_t)(n10 + ty * 4 + p) * NN + n20 + tx * 4)) = o;
    }
}

extern "C" void kernel_launch(void* const* d_in, const int* in_sizes, int n_in,
                              void* d_out, int out_size)
{
    const float* nodes = (const float*)d_in[0];
    const float* sW1   = (const float*)d_in[1];
    const float* sb1   = (const float*)d_in[2];
    const float* sW2   = (const float*)d_in[3];
    const float* sb2   = (const float*)d_in[4];
    const float* tW1   = (const float*)d_in[5];
    const float* tb1   = (const float*)d_in[6];
    const float* tW2   = (const float*)d_in[7];
    const float* tb2   = (const float*)d_in[8];
    const float* anS   = (const float*)d_in[9];
    const float* anT   = (const float*)d_in[10];
    const float* loc   = (const float*)d_in[11];
    const float* lsc   = (const float*)d_in[12];
    const float* S_unc = (const float*)d_in[13];
    float* out = (float*)d_out;

    repack_kernel<<<C * K, 128>>>(sW1, sb1, sW2, sb2, tW1, tb1, tW2, tb2, anS, anT);
    dim3 fg(NN / 32, C);                 // 64 x 8 = 512 blocks, 64 thr, npt=2
    flow_kernel<<<fg, 64>>>(nodes, loc, lsc);
    norm_kernel<<<1, 256>>>(S_unc);
    dim3 og(NN / 64, NN / 64);
    out_kernel<<<og, 256>>>(out);
}

// round 8
// speedup vs baseline: 1.7852x; 1.7852x over previous
#include <cuda_runtime.h>

#define DEV_INLINE __device__ __forceinline__
typedef unsigned long long ull;

constexpr int C  = 8;
constexpr int K  = 64;
constexpr int NN = 2048;

// ---- per-(c,k) repacked blob layout (floats) ----
constexpr int BLOB = 5632;               // 22528 B = 1408 x 16B chunks; /128 thr = 11
constexpr int W1S = 0;                   // [64][20] stride-padded, cols 0..15 valid
constexpr int W1T = 1280;
constexpr int W2S = 2560;                // transposed [i][r], stride 20
constexpr int W2T = 3840;
constexpr int B1S = 5120, B1T = 5184;
constexpr int B2S = 5248, B2T = 5264;    // passive order
constexpr int ANE = 5280;                // [act 16 | pas 16] exp(-s)
constexpr int ANF = 5312;                // [act 16 | pas 16] -t*exp(-s)
constexpr int ASUM = 5344;

__device__ float g_blob[C * K * BLOB];
__device__ float g_Bm[C * NN];
__device__ float g_Sn[C * C];

// ---------- packed f32x2 helpers ----------
DEV_INLINE ull pack2(float lo, float hi) {
    ull r; asm("mov.b64 %0, {%1,%2};" : "=l"(r) : "f"(lo), "f"(hi)); return r;
}
DEV_INLINE void unpack2(ull v, float& lo, float& hi) {
    asm("mov.b64 {%0,%1}, %2;" : "=f"(lo), "=f"(hi) : "l"(v));
}
DEV_INLINE ull ffma2(ull a, ull b, ull c) {
    ull d; asm("fma.rn.f32x2 %0, %1, %2, %3;" : "=l"(d) : "l"(a), "l"(b), "l"(c)); return d;
}
DEV_INLINE ull add2(ull a, ull b) {
    ull d; asm("add.rn.f32x2 %0, %1, %2;" : "=l"(d) : "l"(a), "l"(b)); return d;
}
DEV_INLINE ull mul2(ull a, ull b) {
    ull d; asm("mul.rn.f32x2 %0, %1, %2;" : "=l"(d) : "l"(a), "l"(b)); return d;
}
DEV_INLINE ull neg2(ull a) { return a ^ 0x8000000080000000ULL; }

// ---------- cp.async staging ----------
DEV_INLINE void stage(float* sdst, const float* gsrc, int tid) {
    unsigned sa = (unsigned)__cvta_generic_to_shared(sdst);
    #pragma unroll
    for (int i = 0; i < 11; i++) {
        int ch = tid + i * 128;
        asm volatile("cp.async.cg.shared.global [%0], [%1], 16;"
                     :: "r"(sa + ch * 16), "l"(gsrc + ch * 4));
    }
    asm volatile("cp.async.commit_group;");
}
DEV_INLINE void wait_stage() {
    asm volatile("cp.async.wait_group 0;" ::: "memory");
}

// ---------- repack: gather/compact/transpose weights once ----------
__global__ void __launch_bounds__(128)
repack_kernel(const float* __restrict__ sW1, const float* __restrict__ sb1,
              const float* __restrict__ sW2, const float* __restrict__ sb2,
              const float* __restrict__ tW1, const float* __restrict__ tb1,
              const float* __restrict__ tW2, const float* __restrict__ tb2,
              const float* __restrict__ anS, const float* __restrict__ anT)
{
    const int ck = blockIdx.x;          // c*64+k
    const int k = ck & 63;
    const int A = k & 1, PO = 1 - A;    // active / passive parity
    float* B = g_blob + (size_t)ck * BLOB;
    const int tid = threadIdx.x;
    const size_t wo = (size_t)ck * 2048;

    for (int idx = tid; idx < 1024; idx += 128) {
        int i = idx >> 4, j = idx & 15;
        B[W1S + i * 20 + j] = sW1[wo + i * 32 + 2 * j + A];
        B[W1T + i * 20 + j] = tW1[wo + i * 32 + 2 * j + A];
        B[W2S + i * 20 + j] = sW2[wo + (2 * j + PO) * 64 + i];
        B[W2T + i * 20 + j] = tW2[wo + (2 * j + PO) * 64 + i];
    }
    if (tid < 64) {
        B[B1S + tid] = sb1[ck * 64 + tid];
        B[B1T + tid] = tb1[ck * 64 + tid];
    } else if (tid < 80) {
        int r = tid - 64;
        B[B2S + r] = sb2[ck * 32 + 2 * r + PO];
        B[B2T + r] = tb2[ck * 32 + 2 * r + PO];
    } else if (tid < 112) {
        int q = tid - 80;               // 0..31: [act 16 | pas 16]
        int dim = (q < 16) ? (2 * q + A) : (2 * (q - 16) + PO);
        float a = anS[ck * 32 + dim];
        float t = anT[ck * 32 + dim];
        float e = __expf(-a);
        B[ANE + q] = e;
        B[ANF + q] = -t * e;
    } else if (tid == 112) {
        float s = 0.f;
        for (int d = 0; d < 32; d++) s += anS[ck * 32 + d];
        B[ASUM] = s;
    }
}

// ---------- one inverse layer ----------
// 8 threads per node pair: q = hidden quarter (tid&3), m = mlp select (0=s,1=t).
// Each thread: 2 nodes, one MLP, 16 hidden units. Butterfly over q, exchange
// e^{-s} <-> t over m. SEPARATE log-dets ld0/ld1 per node (R7 bugfix).
DEV_INLINE void layer_compute(const float* __restrict__ sb, int q, int m,
                              ull (&a0)[8], ull (&p0)[8],
                              ull (&a1)[8], ull (&p1)[8],
                              float& ld0, float& ld1)
{
    // ActNorm inverse (E/F stored in act|pas order) — all threads, both nodes
    const ull* E = (const ull*)(sb + ANE);
    const ull* F = (const ull*)(sb + ANF);
    #pragma unroll
    for (int j = 0; j < 8; j++) {
        ull e = E[j], f = F[j];
        a0[j] = ffma2(a0[j], e, f);
        a1[j] = ffma2(a1[j], e, f);
        ull e2 = E[8 + j], f2 = F[8 + j];
        p0[j] = ffma2(p0[j], e2, f2);
        p1[j] = ffma2(p1[j], e2, f2);
    }
    float asum = sb[ASUM];
    ld0 -= asum;
    ld1 -= asum;

    // this thread's MLP weight banks
    const float* w1 = sb + (m ? W1T : W1S);
    const float* w2 = sb + (m ? W2T : W2S);
    const float* b1 = sb + (m ? B1T : B1S);
    const ull*   b2 = (const ull*)(sb + (m ? B2T : B2S));

    // 16 outputs as 8 packed pairs, per node
    ull acc0[8], acc1[8];
    #pragma unroll
    for (int j = 0; j < 8; j++) {
        ull b = (q == 0) ? b2[j] : 0ULL;
        acc0[j] = b; acc1[j] = b;
    }

    #pragma unroll 4
    for (int il = 0; il < 16; il++) {
        const int gi = il * 4 + q;                  // this thread's hidden unit
        const ulonglong2* r1 = (const ulonglong2*)(w1 + gi * 20);
        ull h0 = pack2(b1[gi], 0.f);
        ull h1 = h0;
        #pragma unroll
        for (int ch = 0; ch < 2; ch++) {
            ulonglong2 wa = r1[2 * ch], wb = r1[2 * ch + 1];
            h0 = ffma2(wa.x, a0[4 * ch],     h0);
            h0 = ffma2(wa.y, a0[4 * ch + 1], h0);
            h0 = ffma2(wb.x, a0[4 * ch + 2], h0);
            h0 = ffma2(wb.y, a0[4 * ch + 3], h0);
            h1 = ffma2(wa.x, a1[4 * ch],     h1);
            h1 = ffma2(wa.y, a1[4 * ch + 1], h1);
            h1 = ffma2(wb.x, a1[4 * ch + 2], h1);
            h1 = ffma2(wb.y, a1[4 * ch + 3], h1);
        }
        float x0, x1;
        unpack2(h0, x0, x1); float hv0 = fmaxf(x0 + x1, 0.f);
        unpack2(h1, x0, x1); float hv1 = fmaxf(x0 + x1, 0.f);
        ull h0p = pack2(hv0, hv0), h1p = pack2(hv1, hv1);

        const ulonglong2* r2 = (const ulonglong2*)(w2 + gi * 20);
        #pragma unroll
        for (int ch = 0; ch < 4; ch++) {
            ulonglong2 w = r2[ch];
            acc0[2 * ch]     = ffma2(w.x, h0p, acc0[2 * ch]);
            acc0[2 * ch + 1] = ffma2(w.y, h0p, acc0[2 * ch + 1]);
            acc1[2 * ch]     = ffma2(w.x, h1p, acc1[2 * ch]);
            acc1[2 * ch + 1] = ffma2(w.y, h1p, acc1[2 * ch + 1]);
        }
    }

    // butterfly over the 4 quarter-threads (same m)
    #pragma unroll
    for (int j = 0; j < 8; j++) {
        acc0[j] = add2(acc0[j], __shfl_xor_sync(0xffffffffu, acc0[j], 1));
        acc0[j] = add2(acc0[j], __shfl_xor_sync(0xffffffffu, acc0[j], 2));
        acc1[j] = add2(acc1[j], __shfl_xor_sync(0xffffffffu, acc1[j], 1));
        acc1[j] = add2(acc1[j], __shfl_xor_sync(0xffffffffu, acc1[j], 2));
    }

    // exchange across m (xor 4): s-thread sends e^{-s}, t-thread sends t.
    // Both sides then apply the identical passive update.
    #pragma unroll
    for (int j = 0; j < 8; j++) {
        {   // node 0
            float x0, x1;
            unpack2(acc0[j], x0, x1);
            ull e2o = pack2(__expf(-x0), __expf(-x1));   // valid on m==0
            if (m == 0) ld0 -= (x0 + x1);                // node-0 log-det only
            ull send = (m == 0) ? e2o : acc0[j];
            ull recv = __shfl_xor_sync(0xffffffffu, send, 4);
            ull e2v  = (m == 0) ? e2o : recv;
            ull tv   = (m == 0) ? recv : acc0[j];
            p0[j] = ffma2(p0[j], e2v, neg2(mul2(tv, e2v)));
        }
        {   // node 1
            float x0, x1;
            unpack2(acc1[j], x0, x1);
            ull e2o = pack2(__expf(-x0), __expf(-x1));
            if (m == 0) ld1 -= (x0 + x1);                // node-1 log-det only
            ull send = (m == 0) ? e2o : acc1[j];
            ull recv = __shfl_xor_sync(0xffffffffu, send, 4);
            ull e2v  = (m == 0) ? e2o : recv;
            ull tv   = (m == 0) ? recv : acc1[j];
            p1[j] = ffma2(p1[j], e2v, neg2(mul2(tv, e2v)));
        }
    }
}

__global__ void __launch_bounds__(128)
flow_kernel(const float* __restrict__ nodes,
            const float* __restrict__ loc, const float* __restrict__ lsc)
{
    __shared__ __align__(16) float sbuf[2][BLOB];
    const int tid  = threadIdx.x;
    const int q    = tid & 3;            // hidden quarter
    const int m    = (tid >> 2) & 1;     // 0 = s-MLP, 1 = t-MLP
    const int slot = tid >> 3;           // 0..15
    const int c    = blockIdx.y;
    const int n0   = blockIdx.x * 32 + slot;
    const int n1   = n0 + 16;

    // z packed by parity: ze[j]=(dims 4j,4j+2), zo[j]=(4j+1,4j+3)
    ull ze0[8], zo0[8], ze1[8], zo1[8];
    {
        const float4* np = (const float4*)(nodes + (size_t)n0 * 32);
        #pragma unroll
        for (int j = 0; j < 8; j++) {
            float4 v = np[j];
            ze0[j] = pack2(v.x, v.z); zo0[j] = pack2(v.y, v.w);
        }
        np = (const float4*)(nodes + (size_t)n1 * 32);
        #pragma unroll
        for (int j = 0; j < 8; j++) {
            float4 v = np[j];
            ze1[j] = pack2(v.x, v.z); zo1[j] = pack2(v.y, v.w);
        }
    }
    float ld0 = 0.f, ld1 = 0.f;

    const float* gb = g_blob + (size_t)(c * 64) * BLOB;

    stage(sbuf[0], gb + (size_t)63 * BLOB, tid);
    wait_stage();
    __syncthreads();

    #pragma unroll 1
    for (int k = 63; k > 0; k -= 2) {
        stage(sbuf[1], gb + (size_t)(k - 1) * BLOB, tid);
        // layer k (odd): active = odd dims
        layer_compute(sbuf[0], q, m, zo0, ze0, zo1, ze1, ld0, ld1);
        wait_stage();
        __syncthreads();
        if (k >= 3) stage(sbuf[0], gb + (size_t)(k - 2) * BLOB, tid);
        // layer k-1 (even): active = even dims
        layer_compute(sbuf[1], q, m, ze0, zo0, ze1, zo1, ld0, ld1);
        wait_stage();
        __syncthreads();
    }

    // DiagGaussian log_prob (redundant; written by q==0 && m==0)
    float acc0 = 0.f, acc1 = 0.f;
    const float* lp = loc + c * 32;
    const float* sp = lsc + c * 32;
    #pragma unroll
    for (int j = 0; j < 8; j++) {
        float e0, e1, o0, o1;
        float z40[4], z41[4];
        unpack2(ze0[j], e0, e1); unpack2(zo0[j], o0, o1);
        z40[0] = e0; z40[1] = o0; z40[2] = e1; z40[3] = o1;
        unpack2(ze1[j], e0, e1); unpack2(zo1[j], o0, o1);
        z41[0] = e0; z41[1] = o0; z41[2] = e1; z41[3] = o1;
        #pragma unroll
        for (int b = 0; b < 4; b++) {
            int d = 4 * j + b;
            float ls = __ldg(sp + d);
            float es = __expf(-ls);
            float lc = __ldg(lp + d);
            float u0 = (z40[b] - lc) * es;
            float u1 = (z41[b] - lc) * es;
            acc0 += ls + 0.5f * u0 * u0;
            acc1 += ls + 0.5f * u1 * u1;
        }
    }
    if (q == 0 && m == 0) {
        g_Bm[c * NN + n0] = __expf(ld0 - 29.406037829f - acc0);
        g_Bm[c * NN + n1] = __expf(ld1 - 29.406037829f - acc1);
    }
}

// Fold L1 row-normalizers and softmax-normalized S into one 8x8 matrix.
__global__ void norm_kernel(const float* __restrict__ S_unc)
{
    __shared__ float sh_r[8];
    __shared__ float sh_e[64];
    const int tid = threadIdx.x;
    const int w = tid >> 5, lane = tid & 31;

    float s = 0.f;
    for (int i = lane; i < NN; i += 32) s += g_Bm[w * NN + i];
    #pragma unroll
    for (int o = 16; o; o >>= 1) s += __shfl_xor_sync(0xffffffffu, s, o);
    if (lane == 0) sh_r[w] = fmaxf(s, 1e-12f);
    if (tid < 64) sh_e[tid] = expf(S_unc[tid]);
    __syncthreads();
    if (tid < 64) {
        float tot = 0.f;
        #pragma unroll
        for (int i = 0; i < 64; i++) tot += sh_e[i];
        int c1 = tid >> 3, c2 = tid & 7;
        g_Sn[tid] = sh_e[tid] / (tot * sh_r[c1] * sh_r[c2]);
    }
}

__global__ void __launch_bounds__(256)
out_kernel(float* __restrict__ out)
{
    __shared__ float B1[8][64];
    __shared__ float B2[8][64];
    __shared__ float T2[8][64];
    const int tid = threadIdx.x;
    const int n10 = blockIdx.y * 64;
    const int n20 = blockIdx.x * 64;

    for (int t = tid; t < 512; t += 256) {
        int cc = t >> 6, j = t & 63;
        B1[cc][j] = g_Bm[cc * NN + n10 + j];
        B2[cc][j] = g_Bm[cc * NN + n20 + j];
    }
    __syncthreads();
    if (tid < 64) {
        #pragma unroll
        for (int c1 = 0; c1 < 8; c1++) {
            float a = 0.f;
            #pragma unroll
            for (int c2 = 0; c2 < 8; c2++)
                a = fmaf(g_Sn[c1 * 8 + c2], B2[c2][tid], a);
            T2[c1][tid] = a;
        }
    }
    __syncthreads();

    const int ty = tid >> 4, tx = tid & 15;
    float bv[4][8], tv[8][4];
    #pragma unroll
    for (int cc = 0; cc < 8; cc++) {
        #pragma unroll
        for (int p = 0; p < 4; p++) {
            bv[p][cc] = B1[cc][ty * 4 + p];
            tv[cc][p] = T2[cc][tx * 4 + p];
        }
    }
    #pragma unroll
    for (int p = 0; p < 4; p++) {
        float4 o = {0.f, 0.f, 0.f, 0.f};
        #pragma unroll
        for (int cc = 0; cc < 8; cc++) {
            o.x = fmaf(bv[p][cc], tv[cc][0], o.x);
            o.y = fmaf(bv[p][cc], tv[cc][1], o.y);
            o.z = fmaf(bv[p][cc], tv[cc][2], o.z);
            o.w = fmaf(bv[p][cc], tv[cc][3], o.w);
        }
        *((float4*)(out + (size_t)(n10 + ty * 4 + p) * NN + n20 + tx * 4)) = o;
    }
}

extern "C" void kernel_launch(void* const* d_in, const int* in_sizes, int n_in,
                              void* d_out, int out_size)
{
    const float* nodes = (const float*)d_in[0];
    const float* sW1   = (const float*)d_in[1];
    const float* sb1   = (const float*)d_in[2];
    const float* sW2   = (const float*)d_in[3];
    const float* sb2   = (const float*)d_in[4];
    const float* tW1   = (const float*)d_in[5];
    const float* tb1   = (const float*)d_in[6];
    const float* tW2   = (const float*)d_in[7];
    const float* tb2   = (const float*)d_in[8];
    const float* anS   = (const float*)d_in[9];
    const float* anT   = (const float*)d_in[10];
    const float* loc   = (const float*)d_in[11];
    const float* lsc   = (const float*)d_in[12];
    const float* S_unc = (const float*)d_in[13];
    float* out = (float*)d_out;

    repack_kernel<<<C * K, 128>>>(sW1, sb1, sW2, sb2, tW1, tb1, tW2, tb2, anS, anT);
    dim3 fg(NN / 32, C);                 // 64 x 8 = 512 blocks, 8 thr per node-pair
    flow_kernel<<<fg, 128>>>(nodes, loc, lsc);
    norm_kernel<<<1, 256>>>(S_unc);
    dim3 og(NN / 64, NN / 64);
    out_kernel<<<og, 256>>>(out);
}

// round 9
// speedup vs baseline: 3.4118x; 1.9111x over previous
#include <cuda_runtime.h>

#define DEV_INLINE __device__ __forceinline__
typedef unsigned long long ull;

constexpr int C  = 8;
constexpr int K  = 64;
constexpr int NN = 2048;

// ---- per-(c,k) repacked blob layout (floats) ----
constexpr int BLOB = 5632;               // 22528 B = 1408 x 16B chunks; /64 thr = 22
constexpr int W1S = 0;                   // [64][20] stride-padded, cols 0..15 valid
constexpr int W1T = 1280;
constexpr int W2S = 2560;                // transposed [i][r], stride 20
constexpr int W2T = 3840;
constexpr int B1S = 5120, B1T = 5184;
constexpr int B2S = 5248, B2T = 5264;    // passive order
constexpr int ANE = 5280;                // [act 16 | pas 16] exp(-s)
constexpr int ANF = 5312;                // [act 16 | pas 16] -t*exp(-s)
constexpr int ASUM = 5344;

__device__ float g_blob[C * K * BLOB];
__device__ float g_Bm[C * NN];
__device__ float g_Sn[C * C];

// ---------- packed f32x2 helpers ----------
DEV_INLINE ull pack2(float lo, float hi) {
    ull r; asm("mov.b64 %0, {%1,%2};" : "=l"(r) : "f"(lo), "f"(hi)); return r;
}
DEV_INLINE void unpack2(ull v, float& lo, float& hi) {
    asm("mov.b64 {%0,%1}, %2;" : "=f"(lo), "=f"(hi) : "l"(v));
}
DEV_INLINE ull ffma2(ull a, ull b, ull c) {
    ull d; asm("fma.rn.f32x2 %0, %1, %2, %3;" : "=l"(d) : "l"(a), "l"(b), "l"(c)); return d;
}
DEV_INLINE ull add2(ull a, ull b) {
    ull d; asm("add.rn.f32x2 %0, %1, %2;" : "=l"(d) : "l"(a), "l"(b)); return d;
}
DEV_INLINE ull mul2(ull a, ull b) {
    ull d; asm("mul.rn.f32x2 %0, %1, %2;" : "=l"(d) : "l"(a), "l"(b)); return d;
}
DEV_INLINE ull neg2(ull a) { return a ^ 0x8000000080000000ULL; }

// ---------- cp.async staging (64-thread block: 22 chunks each) ----------
DEV_INLINE void stage(float* sdst, const float* gsrc, int tid) {
    unsigned sa = (unsigned)__cvta_generic_to_shared(sdst);
    #pragma unroll
    for (int i = 0; i < 22; i++) {
        int ch = tid + i * 64;
        asm volatile("cp.async.cg.shared.global [%0], [%1], 16;"
                     :: "r"(sa + ch * 16), "l"(gsrc + ch * 4));
    }
    asm volatile("cp.async.commit_group;");
}
DEV_INLINE void wait_stage() {
    asm volatile("cp.async.wait_group 0;" ::: "memory");
}

// ---------- repack: gather/compact/transpose weights once ----------
__global__ void __launch_bounds__(128)
repack_kernel(const float* __restrict__ sW1, const float* __restrict__ sb1,
              const float* __restrict__ sW2, const float* __restrict__ sb2,
              const float* __restrict__ tW1, const float* __restrict__ tb1,
              const float* __restrict__ tW2, const float* __restrict__ tb2,
              const float* __restrict__ anS, const float* __restrict__ anT)
{
    const int ck = blockIdx.x;          // c*64+k
    const int k = ck & 63;
    const int A = k & 1, PO = 1 - A;    // active / passive parity
    float* B = g_blob + (size_t)ck * BLOB;
    const int tid = threadIdx.x;
    const size_t wo = (size_t)ck * 2048;

    for (int idx = tid; idx < 1024; idx += 128) {
        int i = idx >> 4, j = idx & 15;
        B[W1S + i * 20 + j] = sW1[wo + i * 32 + 2 * j + A];
        B[W1T + i * 20 + j] = tW1[wo + i * 32 + 2 * j + A];
        B[W2S + i * 20 + j] = sW2[wo + (2 * j + PO) * 64 + i];
        B[W2T + i * 20 + j] = tW2[wo + (2 * j + PO) * 64 + i];
    }
    if (tid < 64) {
        B[B1S + tid] = sb1[ck * 64 + tid];
        B[B1T + tid] = tb1[ck * 64 + tid];
    } else if (tid < 80) {
        int r = tid - 64;
        B[B2S + r] = sb2[ck * 32 + 2 * r + PO];
        B[B2T + r] = tb2[ck * 32 + 2 * r + PO];
    } else if (tid < 112) {
        int q = tid - 80;               // 0..31: [act 16 | pas 16]
        int dim = (q < 16) ? (2 * q + A) : (2 * (q - 16) + PO);
        float a = anS[ck * 32 + dim];
        float t = anT[ck * 32 + dim];
        float e = __expf(-a);
        B[ANE + q] = e;
        B[ANF + q] = -t * e;
    } else if (tid == 112) {
        float s = 0.f;
        for (int d = 0; d < 32; d++) s += anS[ck * 32 + d];
        B[ASUM] = s;
    }
}

// ---------- one inverse layer: quarter-split hidden, 2 nodes/thread ----------
DEV_INLINE void layer_compute(const float* __restrict__ sb, int q,
                              ull (&a0)[8], ull (&p0)[8],
                              ull (&a1)[8], ull (&p1)[8],
                              float& ld0, float& ld1)
{
    // ActNorm inverse (E/F stored in act|pas order)
    const ull* E = (const ull*)(sb + ANE);
    const ull* F = (const ull*)(sb + ANF);
    #pragma unroll
    for (int j = 0; j < 8; j++) {
        ull e = E[j], f = F[j];
        a0[j] = ffma2(a0[j], e, f);
        a1[j] = ffma2(a1[j], e, f);
        ull e2 = E[8 + j], f2 = F[8 + j];
        p0[j] = ffma2(p0[j], e2, f2);
        p1[j] = ffma2(p1[j], e2, f2);
    }
    float asum = sb[ASUM];
    ld0 -= asum; ld1 -= asum;

    // accumulators (16 outputs as 8 packed pairs) per node
    ull s0[8], t0[8], s1[8], t1[8];
    const ull* b2s = (const ull*)(sb + B2S);
    const ull* b2t = (const ull*)(sb + B2T);
    #pragma unroll
    for (int j = 0; j < 8; j++) {
        ull bs = (q == 0) ? b2s[j] : 0ULL;
        ull bt = (q == 0) ? b2t[j] : 0ULL;
        s0[j] = bs; s1[j] = bs; t0[j] = bt; t1[j] = bt;
    }

    #pragma unroll 4
    for (int il = 0; il < 16; il++) {
        const int gi = il * 4 + q;                  // this thread's hidden unit
        const ulonglong2* r1s = (const ulonglong2*)(sb + W1S + gi * 20);
        const ulonglong2* r1t = (const ulonglong2*)(sb + W1T + gi * 20);
        ull as0 = pack2(sb[B1S + gi], 0.f);
        ull at0 = pack2(sb[B1T + gi], 0.f);
        ull as1 = as0, at1 = at0;
        #pragma unroll
        for (int ch = 0; ch < 4; ch++) {
            ulonglong2 ws = r1s[ch], wt = r1t[ch];
            as0 = ffma2(ws.x, a0[2*ch],   as0);
            as0 = ffma2(ws.y, a0[2*ch+1], as0);
            as1 = ffma2(ws.x, a1[2*ch],   as1);
            as1 = ffma2(ws.y, a1[2*ch+1], as1);
            at0 = ffma2(wt.x, a0[2*ch],   at0);
            at0 = ffma2(wt.y, a0[2*ch+1], at0);
            at1 = ffma2(wt.x, a1[2*ch],   at1);
            at1 = ffma2(wt.y, a1[2*ch+1], at1);
        }
        float x0, x1;
        unpack2(as0, x0, x1); float hs0 = fmaxf(x0 + x1, 0.f);
        unpack2(as1, x0, x1); float hs1 = fmaxf(x0 + x1, 0.f);
        unpack2(at0, x0, x1); float ht0 = fmaxf(x0 + x1, 0.f);
        unpack2(at1, x0, x1); float ht1 = fmaxf(x0 + x1, 0.f);
        ull hs0p = pack2(hs0, hs0), hs1p = pack2(hs1, hs1);
        ull ht0p = pack2(ht0, ht0), ht1p = pack2(ht1, ht1);

        const ulonglong2* r2s = (const ulonglong2*)(sb + W2S + gi * 20);
        const ulonglong2* r2t = (const ulonglong2*)(sb + W2T + gi * 20);
        #pragma unroll
        for (int ch = 0; ch < 4; ch++) {
            ulonglong2 ws = r2s[ch], wt = r2t[ch];
            s0[2*ch]   = ffma2(ws.x, hs0p, s0[2*ch]);
            s0[2*ch+1] = ffma2(ws.y, hs0p, s0[2*ch+1]);
            s1[2*ch]   = ffma2(ws.x, hs1p, s1[2*ch]);
            s1[2*ch+1] = ffma2(ws.y, hs1p, s1[2*ch+1]);
            t0[2*ch]   = ffma2(wt.x, ht0p, t0[2*ch]);
            t0[2*ch+1] = ffma2(wt.y, ht0p, t0[2*ch+1]);
            t1[2*ch]   = ffma2(wt.x, ht1p, t1[2*ch]);
            t1[2*ch+1] = ffma2(wt.y, ht1p, t1[2*ch+1]);
        }
    }

    // butterfly over the 4 quarter-threads
    #pragma unroll
    for (int j = 0; j < 8; j++) {
        s0[j] = add2(s0[j], __shfl_xor_sync(0xffffffffu, s0[j], 1));
        s0[j] = add2(s0[j], __shfl_xor_sync(0xffffffffu, s0[j], 2));
        t0[j] = add2(t0[j], __shfl_xor_sync(0xffffffffu, t0[j], 1));
        t0[j] = add2(t0[j], __shfl_xor_sync(0xffffffffu, t0[j], 2));
        s1[j] = add2(s1[j], __shfl_xor_sync(0xffffffffu, s1[j], 1));
        s1[j] = add2(s1[j], __shfl_xor_sync(0xffffffffu, s1[j], 2));
        t1[j] = add2(t1[j], __shfl_xor_sync(0xffffffffu, t1[j], 1));
        t1[j] = add2(t1[j], __shfl_xor_sync(0xffffffffu, t1[j], 2));
    }

    // passive update + logdet (redundant across quarters, consistent)
    #pragma unroll
    for (int j = 0; j < 8; j++) {
        float sa, sbv;
        unpack2(s0[j], sa, sbv);
        ld0 -= (sa + sbv);
        ull e2 = pack2(__expf(-sa), __expf(-sbv));
        p0[j] = ffma2(p0[j], e2, neg2(mul2(t0[j], e2)));
        unpack2(s1[j], sa, sbv);
        ld1 -= (sa + sbv);
        e2 = pack2(__expf(-sa), __expf(-sbv));
        p1[j] = ffma2(p1[j], e2, neg2(mul2(t1[j], e2)));
    }
}

__global__ void __launch_bounds__(64)
flow_kernel(const float* __restrict__ nodes,
            const float* __restrict__ loc, const float* __restrict__ lsc)
{
    __shared__ __align__(16) float sbuf[2][BLOB];
    const int tid  = threadIdx.x;
    const int q    = tid & 3;            // quarter of hidden units
    const int slot = tid >> 2;           // 0..15
    const int c    = blockIdx.y;
    const int n0   = blockIdx.x * 32 + slot;
    const int n1   = n0 + 16;

    // z packed by parity: ze[j]=(dims 4j,4j+2), zo[j]=(4j+1,4j+3)
    ull ze0[8], zo0[8], ze1[8], zo1[8];
    {
        const float4* np = (const float4*)(nodes + (size_t)n0 * 32);
        #pragma unroll
        for (int j = 0; j < 8; j++) {
            float4 v = np[j];
            ze0[j] = pack2(v.x, v.z); zo0[j] = pack2(v.y, v.w);
        }
        np = (const float4*)(nodes + (size_t)n1 * 32);
        #pragma unroll
        for (int j = 0; j < 8; j++) {
            float4 v = np[j];
            ze1[j] = pack2(v.x, v.z); zo1[j] = pack2(v.y, v.w);
        }
    }
    float ld0 = 0.f, ld1 = 0.f;

    const float* gb = g_blob + (size_t)(c * 64) * BLOB;

    stage(sbuf[0], gb + (size_t)63 * BLOB, tid);
    wait_stage();
    __syncthreads();

    #pragma unroll 1
    for (int k = 63; k > 0; k -= 2) {
        stage(sbuf[1], gb + (size_t)(k - 1) * BLOB, tid);
        // layer k (odd): active = odd dims
        layer_compute(sbuf[0], q, zo0, ze0, zo1, ze1, ld0, ld1);
        wait_stage();
        __syncthreads();
        if (k >= 3) stage(sbuf[0], gb + (size_t)(k - 2) * BLOB, tid);
        // layer k-1 (even): active = even dims
        layer_compute(sbuf[1], q, ze0, zo0, ze1, zo1, ld0, ld1);
        wait_stage();
        __syncthreads();
    }

    // DiagGaussian log_prob
    float acc0 = 0.f, acc1 = 0.f;
    const float* lp = loc + c * 32;
    const float* sp = lsc + c * 32;
    #pragma unroll
    for (int j = 0; j < 8; j++) {
        float e0, e1, o0, o1;
        float z40[4], z41[4];
        unpack2(ze0[j], e0, e1); unpack2(zo0[j], o0, o1);
        z40[0] = e0; z40[1] = o0; z40[2] = e1; z40[3] = o1;
        unpack2(ze1[j], e0, e1); unpack2(zo1[j], o0, o1);
        z41[0] = e0; z41[1] = o0; z41[2] = e1; z41[3] = o1;
        #pragma unroll
        for (int b = 0; b < 4; b++) {
            int d = 4 * j + b;
            float ls = __ldg(sp + d);
            float es = __expf(-ls);
            float lc = __ldg(lp + d);
            float u0 = (z40[b] - lc) * es;
            float u1 = (z41[b] - lc) * es;
            acc0 += ls + 0.5f * u0 * u0;
            acc1 += ls + 0.5f * u1 * u1;
        }
    }
    if (q == 0) {
        g_Bm[c * NN + n0] = __expf(ld0 - 29.406037829f - acc0);
        g_Bm[c * NN + n1] = __expf(ld1 - 29.406037829f - acc1);
    }
}

// Fold L1 row-normalizers and softmax-normalized S into one 8x8 matrix.
__global__ void norm_kernel(const float* __restrict__ S_unc)
{
    __shared__ float sh_r[8];
    __shared__ float sh_e[64];
    const int tid = threadIdx.x;
    const int w = tid >> 5, lane = tid & 31;

    float s = 0.f;
    for (int i = lane; i < NN; i += 32) s += g_Bm[w * NN + i];
    #pragma unroll
    for (int o = 16; o; o >>= 1) s += __shfl_xor_sync(0xffffffffu, s, o);
    if (lane == 0) sh_r[w] = fmaxf(s, 1e-12f);
    if (tid < 64) sh_e[tid] = expf(S_unc[tid]);
    __syncthreads();
    if (tid < 64) {
        float tot = 0.f;
        #pragma unroll
        for (int i = 0; i < 64; i++) tot += sh_e[i];
        int c1 = tid >> 3, c2 = tid & 7;
        g_Sn[tid] = sh_e[tid] / (tot * sh_r[c1] * sh_r[c2]);
    }
}

__global__ void __launch_bounds__(256)
out_kernel(float* __restrict__ out)
{
    __shared__ float B1[8][64];
    __shared__ float B2[8][64];
    __shared__ float T2[8][64];
    const int tid = threadIdx.x;
    const int n10 = blockIdx.y * 64;
    const int n20 = blockIdx.x * 64;

    for (int t = tid; t < 512; t += 256) {
        int cc = t >> 6, j = t & 63;
        B1[cc][j] = g_Bm[cc * NN + n10 + j];
        B2[cc][j] = g_Bm[cc * NN + n20 + j];
    }
    __syncthreads();
    if (tid < 64) {
        #pragma unroll
        for (int c1 = 0; c1 < 8; c1++) {
            float a = 0.f;
            #pragma unroll
            for (int c2 = 0; c2 < 8; c2++)
                a = fmaf(g_Sn[c1 * 8 + c2], B2[c2][tid], a);
            T2[c1][tid] = a;
        }
    }
    __syncthreads();

    const int ty = tid >> 4, tx = tid & 15;
    float bv[4][8], tv[8][4];
    #pragma unroll
    for (int cc = 0; cc < 8; cc++) {
        #pragma unroll
        for (int p = 0; p < 4; p++) {
            bv[p][cc] = B1[cc][ty * 4 + p];
            tv[cc][p] = T2[cc][tx * 4 + p];
        }
    }
    #pragma unroll
    for (int p = 0; p < 4; p++) {
        float4 o = {0.f, 0.f, 0.f, 0.f};
        #pragma unroll
        for (int cc = 0; cc < 8; cc++) {
            o.x = fmaf(bv[p][cc], tv[cc][0], o.x);
            o.y = fmaf(bv[p][cc], tv[cc][1], o.y);
            o.z = fmaf(bv[p][cc], tv[cc][2], o.z);
            o.w = fmaf(bv[p][cc], tv[cc][3], o.w);
        }
        *((float4*)(out + (size_t)(n10 + ty * 4 + p) * NN + n20 + tx * 4)) = o;
    }
}

extern "C" void kernel_launch(void* const* d_in, const int* in_sizes, int n_in,
                              void* d_out, int out_size)
{
    const float* nodes = (const float*)d_in[0];
    const float* sW1   = (const float*)d_in[1];
    const float* sb1   = (const float*)d_in[2];
    const float* sW2   = (const float*)d_in[3];
    const float* sb2   = (const float*)d_in[4];
    const float* tW1   = (const float*)d_in[5];
    const float* tb1   = (const float*)d_in[6];
    const float* tW2   = (const float*)d_in[7];
    const float* tb2   = (const float*)d_in[8];
    const float* anS   = (const float*)d_in[9];
    const float* anT   = (const float*)d_in[10];
    const float* loc   = (const float*)d_in[11];
    const float* lsc   = (const float*)d_in[12];
    const float* S_unc = (const float*)d_in[13];
    float* out = (float*)d_out;

    repack_kernel<<<C * K, 128>>>(sW1, sb1, sW2, sb2, tW1, tb1, tW2, tb2, anS, anT);
    dim3 fg(NN / 32, C);                 // 64 x 8 = 512 blocks, 64 threads each
    flow_kernel<<<fg, 64>>>(nodes, loc, lsc);
    norm_kernel<<<1, 256>>>(S_unc);
    dim3 og(NN / 64, NN / 64);
    out_kernel<<<og, 256>>>(out);
}